// round 13
// baseline (speedup 1.0000x reference)
#include <cuda_runtime.h>
#include <cuda_fp16.h>
#include <cstdint>

#define DIM   512
#define N_CB  8192
#define M_Z   32768
#define QN    16777216   // M_Z * DIM
#define CAP   32
#define MARGIN 0.5f

// coarse geometry: 256 CTAs x 128 rows (r6 band size), k128 B stages
#define CTA_M       128
#define SMA_BYTES   131072                // A band: 128 rows x 1KB f16
#define SMB_STAGE   32768                 // B stage: 128 codes x 256B (k128)
#define NSTG        3
#define SCNT_OFF    (SMA_BYTES + NSTG * SMB_STAGE)   // 229376
#define COARSE_SMEM (SCNT_OFF + 512)                 // 229888 (<= 232448)
#define NSTAGES_K   256                   // 64 n-tiles * 4 k128-slices

// ---- scratch (device globals; no allocation) ----
__device__ float  g_qcb[(size_t)N_CB * DIM];    // quant_codebook fp32
__device__ float  g_u  [(size_t)N_CB * DIM];    // U fp32 (rescore)
__device__ __half g_ub [(size_t)N_CB * DIM];    // U f16
__device__ __half g_zb [(size_t)M_Z * DIM];     // z f16
__device__ float  g_rs  [N_CB];                 // 1/||c||
__device__ float  g_beta[N_CB];                 // (b . c)/||c||
__device__ unsigned g_cand[(size_t)M_Z * CAP];
__device__ int    g_ccnt[M_Z];
__device__ int    g_idx[M_Z];
__device__ float  g_partial[M_Z];

// ============================================================
// base-ISA PTX helpers
// ============================================================
__device__ __forceinline__ uint32_t smem_u32(const void* p) {
    uint32_t a;
    asm("{ .reg .u64 t; cvta.to.shared.u64 t, %1; cvt.u32.u64 %0, t; }" : "=r"(a) : "l"(p));
    return a;
}
__device__ __forceinline__ void cp16(uint32_t dst, const void* src) {
    asm volatile("cp.async.cg.shared.global [%0], [%1], 16;" :: "r"(dst), "l"(src) : "memory");
}
#define CP_COMMIT() asm volatile("cp.async.commit_group;" ::: "memory")
#define CP_WAIT(N)  asm volatile("cp.async.wait_group %0;" :: "n"(N) : "memory")

__device__ __forceinline__ void ldmatrix_x4(uint32_t* r, uint32_t addr) {
    asm volatile("ldmatrix.sync.aligned.m8n8.x4.shared.b16 {%0,%1,%2,%3}, [%4];"
        : "=r"(r[0]), "=r"(r[1]), "=r"(r[2]), "=r"(r[3]) : "r"(addr));
}
// f16 x f16 -> f16 accumulate (2 accumulator regs per m16n8)
__device__ __forceinline__ void mma_f16(uint32_t& d0, uint32_t& d1,
                                        const uint32_t* a, uint32_t b0, uint32_t b1) {
    asm volatile("mma.sync.aligned.m16n8k16.row.col.f16.f16.f16.f16 "
        "{%0,%1}, {%2,%3,%4,%5}, {%6,%7}, {%0,%1};"
        : "+r"(d0), "+r"(d1)
        : "r"(a[0]), "r"(a[1]), "r"(a[2]), "r"(a[3]), "r"(b0), "r"(b1));
}

// ============================================================
// K1: qcb = emb @ emb_w^T + emb_b   (NT, fp32)
// ============================================================
__global__ __launch_bounds__(256, 2)
void gemm_bias_nt(const float* __restrict__ A, const float* __restrict__ W,
                  const float* __restrict__ bias, int K)
{
    __shared__ float As[16][128];
    __shared__ float Ws[16][128];
    const int tid = threadIdx.x;
    const int tx  = tid & 15;
    const int ty  = tid >> 4;
    const int row0 = blockIdx.y * 128;
    const int col0 = blockIdx.x * 128;

    float acc[8][8];
    #pragma unroll
    for (int i = 0; i < 8; i++)
        #pragma unroll
        for (int j = 0; j < 8; j++) acc[i][j] = 0.0f;

    for (int k0 = 0; k0 < K; k0 += 16) {
        #pragma unroll
        for (int v = tid; v < 512; v += 256) {
            int r  = v >> 2;
            int kc = (v & 3) << 2;
            float4 a = *(const float4*)(A + (size_t)(row0 + r) * K + k0 + kc);
            As[kc + 0][r] = a.x; As[kc + 1][r] = a.y;
            As[kc + 2][r] = a.z; As[kc + 3][r] = a.w;
            float4 w = *(const float4*)(W + (size_t)(col0 + r) * K + k0 + kc);
            Ws[kc + 0][r] = w.x; Ws[kc + 1][r] = w.y;
            Ws[kc + 2][r] = w.z; Ws[kc + 3][r] = w.w;
        }
        __syncthreads();
        #pragma unroll
        for (int kk = 0; kk < 16; kk++) {
            float a[8], b[8];
            *(float4*)(a)     = *(const float4*)&As[kk][ty * 8];
            *(float4*)(a + 4) = *(const float4*)&As[kk][ty * 8 + 4];
            *(float4*)(b)     = *(const float4*)&Ws[kk][tx * 8];
            *(float4*)(b + 4) = *(const float4*)&Ws[kk][tx * 8 + 4];
            #pragma unroll
            for (int i = 0; i < 8; i++)
                #pragma unroll
                for (int j = 0; j < 8; j++)
                    acc[i][j] = fmaf(a[i], b[j], acc[i][j]);
        }
        __syncthreads();
    }

    float bs[8];
    #pragma unroll
    for (int j = 0; j < 8; j++) bs[j] = bias[col0 + tx * 8 + j];

    #pragma unroll
    for (int i = 0; i < 8; i++) {
        size_t row = (size_t)(row0 + ty * 8 + i);
        float* cp = g_qcb + row * DIM + col0 + tx * 8;
        *(float4*)(cp)     = make_float4(acc[i][0]+bs[0], acc[i][1]+bs[1], acc[i][2]+bs[2], acc[i][3]+bs[3]);
        *(float4*)(cp + 4) = make_float4(acc[i][4]+bs[4], acc[i][5]+bs[5], acc[i][6]+bs[6], acc[i][7]+bs[7]);
    }
}

// ============================================================
// K2: per-row 1/||c|| and beta = (z_proj_b . c)/||c||
// ============================================================
__global__ void rownorm_beta(const float* __restrict__ zpb)
{
    int row  = blockIdx.x * 8 + (threadIdx.x >> 5);
    int lane = threadIdx.x & 31;
    const float* x = g_qcb + (size_t)row * DIM;
    float s2 = 0.0f, sb = 0.0f;
    #pragma unroll
    for (int it = 0; it < 4; it++) {
        float4 v = *(const float4*)(x + lane * 4 + it * 128);
        float4 b = *(const float4*)(zpb + lane * 4 + it * 128);
        s2 += v.x*v.x + v.y*v.y + v.z*v.z + v.w*v.w;
        sb += v.x*b.x + v.y*b.y + v.z*b.z + v.w*b.w;
    }
    #pragma unroll
    for (int off = 16; off > 0; off >>= 1) {
        s2 += __shfl_xor_sync(0xFFFFFFFFu, s2, off);
        sb += __shfl_xor_sync(0xFFFFFFFFu, sb, off);
    }
    float rs = 1.0f / fmaxf(sqrtf(s2), 1e-12f);
    if (lane == 0) { g_rs[row] = rs; g_beta[row] = sb * rs; }
}

// ============================================================
// K3: U = (g_qcb @ W) * rs[row]   (NN, fp32) -> g_u fp32 + g_ub f16
// ============================================================
__global__ __launch_bounds__(256, 2)
void gemm_nn_scaled(const float* __restrict__ W)
{
    __shared__ float As[16][128];
    __shared__ float Ws[16][128];
    const int tid = threadIdx.x;
    const int tx  = tid & 15;
    const int ty  = tid >> 4;
    const int row0 = blockIdx.y * 128;
    const int col0 = blockIdx.x * 128;
    const float* __restrict__ A = g_qcb;

    float acc[8][8];
    #pragma unroll
    for (int i = 0; i < 8; i++)
        #pragma unroll
        for (int j = 0; j < 8; j++) acc[i][j] = 0.0f;

    for (int k0 = 0; k0 < DIM; k0 += 16) {
        #pragma unroll
        for (int v = tid; v < 512; v += 256) {
            int r  = v >> 2;
            int kc = (v & 3) << 2;
            float4 a = *(const float4*)(A + (size_t)(row0 + r) * DIM + k0 + kc);
            As[kc + 0][r] = a.x; As[kc + 1][r] = a.y;
            As[kc + 2][r] = a.z; As[kc + 3][r] = a.w;
        }
        #pragma unroll
        for (int v = tid; v < 512; v += 256) {
            int kk = v >> 5;
            int nc = (v & 31) * 4;
            float4 w = *(const float4*)(W + (size_t)(k0 + kk) * DIM + col0 + nc);
            *(float4*)&Ws[kk][nc] = w;
        }
        __syncthreads();
        #pragma unroll
        for (int kk = 0; kk < 16; kk++) {
            float a[8], b[8];
            *(float4*)(a)     = *(const float4*)&As[kk][ty * 8];
            *(float4*)(a + 4) = *(const float4*)&As[kk][ty * 8 + 4];
            *(float4*)(b)     = *(const float4*)&Ws[kk][tx * 8];
            *(float4*)(b + 4) = *(const float4*)&Ws[kk][tx * 8 + 4];
            #pragma unroll
            for (int i = 0; i < 8; i++)
                #pragma unroll
                for (int j = 0; j < 8; j++)
                    acc[i][j] = fmaf(a[i], b[j], acc[i][j]);
        }
        __syncthreads();
    }

    #pragma unroll
    for (int i = 0; i < 8; i++) {
        size_t row = (size_t)(row0 + ty * 8 + i);
        float s = g_rs[row];
        float o[8];
        #pragma unroll
        for (int j = 0; j < 8; j++) o[j] = acc[i][j] * s;
        float* up = g_u + row * DIM + col0 + tx * 8;
        *(float4*)(up)     = make_float4(o[0], o[1], o[2], o[3]);
        *(float4*)(up + 4) = make_float4(o[4], o[5], o[6], o[7]);
        __half2* hp = (__half2*)(g_ub + row * DIM + col0 + tx * 8);
        hp[0] = __floats2half2_rn(o[0], o[1]);
        hp[1] = __floats2half2_rn(o[2], o[3]);
        hp[2] = __floats2half2_rn(o[4], o[5]);
        hp[3] = __floats2half2_rn(o[6], o[7]);
    }
}

// ============================================================
// K4: z -> f16
// ============================================================
__global__ void convert_z(const float* __restrict__ z)
{
    long long n4 = QN / 4;
    long long stride = (long long)gridDim.x * blockDim.x;
    for (long long i = (long long)blockIdx.x * blockDim.x + threadIdx.x; i < n4; i += stride) {
        float4 v = ((const float4*)z)[i];
        __half2 p0 = __floats2half2_rn(v.x, v.y);
        __half2 p1 = __floats2half2_rn(v.z, v.w);
        uint2 o;
        o.x = *(uint32_t*)&p0;
        o.y = *(uint32_t*)&p1;
        ((uint2*)g_zb)[i] = o;
    }
}

// ============================================================
// K5: coarse f16 HMMA pass (r6 band geometry, f16 accumulators,
// k128 B stages in a 3-slot ring). 256 CTAs x 128 rows.
// 8 warps, warp tile m16 x n128.
// ============================================================
__global__ __launch_bounds__(256)
void coarse_kernel()
{
    extern __shared__ char sm[];
    const uint32_t smA = smem_u32(sm);
    int* scnt = (int*)(sm + SCNT_OFF);

    const int tid  = threadIdx.x;
    const int lane = tid & 31;
    const int wid  = tid >> 5;
    const int row0 = blockIdx.x * CTA_M;
    const int warp_m = wid << 4;
    const int l8   = lane & 7;
    const int quad = lane >> 3;
    const int lr0  = warp_m + (lane >> 2);

    if (tid < CTA_M) scnt[tid] = 0;

    // ---- A band: 128 rows x 512 f16 (1KB/row), swizzled ----
    #pragma unroll
    for (int i = 0; i < 32; i++) {
        int idx = tid + (i << 8);
        int r = idx >> 6, c = idx & 63;
        const void* src = g_zb + ((size_t)(row0 + r) << 9) + (c << 3);
        uint32_t byte = ((uint32_t)r << 10) + ((uint32_t)c << 4);
        cp16(smA + (byte ^ ((r & 7) << 4)), src);
    }
    // ---- B stage loader: 128 codes x 128 f16 (256B/row), swizzled ----
    auto load_stage = [&](int gs, int slot) {
        const int n0 = (gs >> 2) << 7, k0 = (gs & 3) << 7;   // k0 in f16 elems
        const uint32_t base = smA + SMA_BYTES + (uint32_t)slot * SMB_STAGE;
        #pragma unroll
        for (int i = 0; i < 8; i++) {
            int idx = tid + (i << 8);
            int r = idx >> 4, c = idx & 15;
            const void* src = g_ub + ((size_t)(n0 + r) << 9) + k0 + (c << 3);
            uint32_t byte = ((uint32_t)r << 8) + ((uint32_t)c << 4);
            cp16(base + (byte ^ ((r & 7) << 4)), src);
        }
    };

    load_stage(0, 0); CP_COMMIT();   // group 0: A band + stage 0
    load_stage(1, 1); CP_COMMIT();

    uint32_t acc0[16], acc1[16];     // f16x2 accumulators: rows lr0 / lr0+8
    #pragma unroll
    for (int i = 0; i < 16; i++) { acc0[i] = 0u; acc1[i] = 0u; }

    float best0 = -3.4e38f, best1 = -3.4e38f;
    int slot_c = 0, slot_l = 2;

    for (int gs = 0; gs < NSTAGES_K; gs++) {
        CP_WAIT(1);
        __syncthreads();

        if (gs + 2 < NSTAGES_K) load_stage(gs + 2, slot_l);
        CP_COMMIT();
        slot_l = (slot_l == 2) ? 0 : slot_l + 1;

        const uint32_t sB = smA + SMA_BYTES + (uint32_t)slot_c * SMB_STAGE;
        slot_c = (slot_c == 2) ? 0 : slot_c + 1;
        const int s2 = gs & 3;                 // k128 slice within the n-tile

        #pragma unroll
        for (int s16 = 0; s16 < 8; s16++) {
            uint32_t a[4];
            {
                int m_r = warp_m + l8 + ((quad & 1) << 3);
                int bc  = s2 * 256 + s16 * 32 + ((quad >> 1) << 4);
                ldmatrix_x4(a, smA + ((((uint32_t)m_r << 10) + bc) ^ ((m_r & 7) << 4)));
            }
            #pragma unroll
            for (int ng = 0; ng < 8; ng++) {
                uint32_t b[4];
                int n_r = (ng << 4) + l8 + ((quad & 1) << 3);
                int bc  = s16 * 32 + ((quad >> 1) << 4);
                ldmatrix_x4(b, sB + ((((uint32_t)n_r << 8) + bc) ^ ((n_r & 7) << 4)));
                mma_f16(acc0[2 * ng],     acc1[2 * ng],     a, b[0], b[2]);
                mma_f16(acc0[2 * ng + 1], acc1[2 * ng + 1], a, b[1], b[3]);
            }
        }

        if ((gs & 3) == 3) {
            // ---- tile epilogue: + beta, running argmax, margin emit ----
            const int n0 = (gs >> 2) << 7;
            float t0 = -3.4e38f, t1 = -3.4e38f;
            float s0v[16], s1v[16], s2v[16], s3v[16];
            #pragma unroll
            for (int ni = 0; ni < 16; ni++) {
                int nb = n0 + (ni << 3) + ((lane & 3) << 1);
                float2 be = *(const float2*)(g_beta + nb);
                float2 f0 = __half22float2(*(__half2*)&acc0[ni]);
                float2 f1 = __half22float2(*(__half2*)&acc1[ni]);
                s0v[ni] = f0.x + be.x; s1v[ni] = f0.y + be.y;
                s2v[ni] = f1.x + be.x; s3v[ni] = f1.y + be.y;
                t0 = fmaxf(t0, fmaxf(s0v[ni], s1v[ni]));
                t1 = fmaxf(t1, fmaxf(s2v[ni], s3v[ni]));
                acc0[ni] = 0u; acc1[ni] = 0u;
            }
            t0 = fmaxf(t0, __shfl_xor_sync(0xFFFFFFFFu, t0, 1));
            t0 = fmaxf(t0, __shfl_xor_sync(0xFFFFFFFFu, t0, 2));
            t1 = fmaxf(t1, __shfl_xor_sync(0xFFFFFFFFu, t1, 1));
            t1 = fmaxf(t1, __shfl_xor_sync(0xFFFFFFFFu, t1, 2));
            best0 = fmaxf(best0, t0);
            best1 = fmaxf(best1, t1);
            const float th0 = best0 - MARGIN, th1 = best1 - MARGIN;
            const int gr0 = row0 + lr0;

            #pragma unroll
            for (int ni = 0; ni < 16; ni++) {
                int nb = n0 + (ni << 3) + ((lane & 3) << 1);
                if (s0v[ni] > th0) {
                    int sl = atomicAdd(&scnt[lr0], 1);
                    if (sl < CAP) g_cand[((size_t)gr0 << 5) + sl] = (unsigned)nb;
                }
                if (s1v[ni] > th0) {
                    int sl = atomicAdd(&scnt[lr0], 1);
                    if (sl < CAP) g_cand[((size_t)gr0 << 5) + sl] = (unsigned)(nb + 1);
                }
                if (s2v[ni] > th1) {
                    int sl = atomicAdd(&scnt[lr0 + 8], 1);
                    if (sl < CAP) g_cand[((size_t)(gr0 + 8) << 5) + sl] = (unsigned)nb;
                }
                if (s3v[ni] > th1) {
                    int sl = atomicAdd(&scnt[lr0 + 8], 1);
                    if (sl < CAP) g_cand[((size_t)(gr0 + 8) << 5) + sl] = (unsigned)(nb + 1);
                }
            }
        }
    }

    __syncthreads();
    if (tid < CTA_M) g_ccnt[row0 + tid] = scnt[tid];
}

// ============================================================
// K6: exact fp32 rescore: s = z . u_n + beta_n.  One warp per z-row.
// ============================================================
__global__ __launch_bounds__(256)
void rescore(const float* __restrict__ z)
{
    const int row  = blockIdx.x * 8 + (threadIdx.x >> 5);
    const int lane = threadIdx.x & 31;
    const float* zp = z + (size_t)row * DIM;
    float4 zr[4];
    #pragma unroll
    for (int it = 0; it < 4; it++)
        zr[it] = *(const float4*)(zp + lane * 16 + it * 4);

    int cnt = g_ccnt[row];
    float bv = -3.4e38f;
    int   bi = 0x7FFFFFFF;

    if (cnt <= CAP) {
        for (int c = 0; c < cnt; c++) {
            int idx = (int)g_cand[((size_t)row << 5) + c];
            const float* ur = g_u + (size_t)idx * DIM;
            float s = 0.0f;
            #pragma unroll
            for (int it = 0; it < 4; it++) {
                float4 uv = *(const float4*)(ur + lane * 16 + it * 4);
                s = fmaf(zr[it].x, uv.x, s);
                s = fmaf(zr[it].y, uv.y, s);
                s = fmaf(zr[it].z, uv.z, s);
                s = fmaf(zr[it].w, uv.w, s);
            }
            #pragma unroll
            for (int o = 16; o > 0; o >>= 1) s += __shfl_xor_sync(0xFFFFFFFFu, s, o);
            s += g_beta[idx];
            if (s > bv || (s == bv && idx < bi)) { bv = s; bi = idx; }
        }
    } else {
        for (int n = 0; n < N_CB; n++) {
            const float* ur = g_u + (size_t)n * DIM;
            float s = 0.0f;
            #pragma unroll
            for (int it = 0; it < 4; it++) {
                float4 uv = *(const float4*)(ur + lane * 16 + it * 4);
                s = fmaf(zr[it].x, uv.x, s);
                s = fmaf(zr[it].y, uv.y, s);
                s = fmaf(zr[it].z, uv.z, s);
                s = fmaf(zr[it].w, uv.w, s);
            }
            #pragma unroll
            for (int o = 16; o > 0; o >>= 1) s += __shfl_xor_sync(0xFFFFFFFFu, s, o);
            s += g_beta[n];
            if (s > bv) { bv = s; bi = n; }
        }
    }
    if (lane == 0) g_idx[row] = bi;
}

// ============================================================
// K7: quantized = z + (q - z), per-row (q-z)^2 partial, idx tail
// ============================================================
__global__ void gather_loss(const float* __restrict__ z, float* __restrict__ out,
                            long long out_size)
{
    int row = blockIdx.x;
    int t   = threadIdx.x;   // 128 threads
    int id  = g_idx[row];
    const float* q  = g_qcb + (size_t)id * DIM;
    const float* zr = z + (size_t)row * DIM;
    float* oq = out + (size_t)row * DIM;

    float s = 0.0f;
    #pragma unroll
    for (int c = t * 4; c < DIM; c += 512) {
        float4 qv = *(const float4*)(q + c);
        float4 zv = *(const float4*)(zr + c);
        float4 o;
        float d;
        d = qv.x - zv.x; o.x = zv.x + d; s = fmaf(d, d, s);
        d = qv.y - zv.y; o.y = zv.y + d; s = fmaf(d, d, s);
        d = qv.z - zv.z; o.z = zv.z + d; s = fmaf(d, d, s);
        d = qv.w - zv.w; o.w = zv.w + d; s = fmaf(d, d, s);
        *(float4*)(oq + c) = o;
    }

    __shared__ float red[128];
    red[t] = s;
    __syncthreads();
    #pragma unroll
    for (int off = 64; off > 0; off >>= 1) {
        if (t < off) red[t] += red[t + off];
        __syncthreads();
    }
    if (t == 0) {
        g_partial[row] = red[0];
        long long pos = (long long)QN + 1 + row;
        if (pos < out_size) out[pos] = (float)id;
    }
}

__global__ void finalize_loss(float* __restrict__ out, long long out_size)
{
    __shared__ float red[256];
    int t = threadIdx.x;
    float s = 0.0f;
    for (int i = t; i < M_Z; i += 256) s += g_partial[i];
    red[t] = s;
    __syncthreads();
    #pragma unroll
    for (int off = 128; off > 0; off >>= 1) {
        if (t < off) red[t] += red[t + off];
        __syncthreads();
    }
    if (t == 0 && (long long)QN < out_size)
        out[QN] = red[0] * (1.25f / 16777216.0f);
}

__global__ void zero_range(float* __restrict__ out, long long begin, long long end)
{
    long long stride = (long long)gridDim.x * blockDim.x;
    for (long long i = begin + (long long)blockIdx.x * blockDim.x + threadIdx.x;
         i < end; i += stride)
        out[i] = 0.0f;
}

// ============================================================
extern "C" void kernel_launch(void* const* d_in, const int* in_sizes, int n_in,
                              void* d_out, int out_size)
{
    const float* z     = (const float*)d_in[0];   // [8,4096,512]
    const float* emb   = (const float*)d_in[1];   // [8192,512]
    const float* emb_w = (const float*)d_in[2];   // [512,512]
    const float* emb_b = (const float*)d_in[3];   // [512]
    const float* zw    = (const float*)d_in[4];   // [512,512]
    const float* zb    = (const float*)d_in[5];   // [512]
    // d_in[6] = l2_scale: positive per-row scaling, argmin-invariant -> unused
    float* out = (float*)d_out;
    long long osz = (long long)out_size;

    cudaFuncSetAttribute(coarse_kernel,
                         cudaFuncAttributeMaxDynamicSharedMemorySize, COARSE_SMEM);

    // K1: quant_codebook = emb @ emb_w^T + emb_b
    gemm_bias_nt<<<dim3(4, 64), 256>>>(emb, emb_w, emb_b, DIM);
    // K2: row norms + beta
    rownorm_beta<<<N_CB / 8, 256>>>(zb);
    // K3: U = diag(1/||c||)(qcb @ zw)
    gemm_nn_scaled<<<dim3(4, 64), 256>>>(zw);
    // K4: z -> f16
    convert_z<<<2048, 256>>>(z);
    // K5: f16 HMMA coarse pass -> candidates
    coarse_kernel<<<M_Z / CTA_M, 256, COARSE_SMEM>>>();
    // K6: exact fp32 rescore -> g_idx
    rescore<<<M_Z / 8, 256>>>(z);
    // K7: outputs
    gather_loss<<<M_Z, 128>>>(z, out, osz);
    finalize_loss<<<1, 256>>>(out, osz);
    long long need = (long long)QN + 1 + M_Z;
    if (osz > need) zero_range<<<256, 256>>>(out, need, osz);
}

// round 16
// speedup vs baseline: 25.7818x; 25.7818x over previous
#include <cuda_runtime.h>
#include <cuda_fp16.h>
#include <cstdint>

#define DIM   512
#define N_CB  8192
#define M_Z   32768
#define QN    16777216   // M_Z * DIM
#define CAP   64
#define MARGIN 0.2f

// coarse geometry: 256 CTAs x 128 rows, k128 B stages, 3-slot ring
#define CTA_M       128
#define SMA_BYTES   131072                // A band: 128 rows x 1KB f16
#define SMB_STAGE   32768                 // B stage: 128 codes x 256B (k128)
#define NSTG        3
#define SCNT_OFF    (SMA_BYTES + NSTG * SMB_STAGE)   // 229376
#define COARSE_SMEM (SCNT_OFF + 512)                 // 229888
#define NSTAGES_K   256                   // 64 n-tiles * 4 k128-slices

// ---- scratch (device globals; no allocation) ----
__device__ float  g_qcb[(size_t)N_CB * DIM];    // quant_codebook fp32
__device__ float  g_u  [(size_t)N_CB * DIM];    // U fp32 (rescore)
__device__ __half g_ub [(size_t)N_CB * DIM];    // U f16
__device__ __half g_zb [(size_t)M_Z * DIM];     // z f16
__device__ float  g_rs  [N_CB];                 // 1/||c||
__device__ float  g_beta[N_CB];                 // (b . c)/||c||
__device__ unsigned g_cand[(size_t)M_Z * CAP];
__device__ int    g_ccnt[M_Z];
__device__ int    g_idx[M_Z];
__device__ float  g_partial[M_Z];

// ============================================================
// base-ISA PTX helpers
// ============================================================
__device__ __forceinline__ uint32_t smem_u32(const void* p) {
    uint32_t a;
    asm("{ .reg .u64 t; cvta.to.shared.u64 t, %1; cvt.u32.u64 %0, t; }" : "=r"(a) : "l"(p));
    return a;
}
__device__ __forceinline__ void cp16(uint32_t dst, const void* src) {
    asm volatile("cp.async.cg.shared.global [%0], [%1], 16;" :: "r"(dst), "l"(src) : "memory");
}
#define CP_COMMIT() asm volatile("cp.async.commit_group;" ::: "memory")
#define CP_WAIT(N)  asm volatile("cp.async.wait_group %0;" :: "n"(N) : "memory")

__device__ __forceinline__ void ldmatrix_x4(uint32_t* r, uint32_t addr) {
    asm volatile("ldmatrix.sync.aligned.m8n8.x4.shared.b16 {%0,%1,%2,%3}, [%4];"
        : "=r"(r[0]), "=r"(r[1]), "=r"(r[2]), "=r"(r[3]) : "r"(addr));
}
// f16 x f16 -> f16 accumulate (2 accumulator regs per m16n8)
__device__ __forceinline__ void mma_f16(uint32_t& d0, uint32_t& d1,
                                        const uint32_t* a, uint32_t b0, uint32_t b1) {
    asm volatile("mma.sync.aligned.m16n8k16.row.col.f16.f16.f16.f16 "
        "{%0,%1}, {%2,%3,%4,%5}, {%6,%7}, {%0,%1};"
        : "+r"(d0), "+r"(d1)
        : "r"(a[0]), "r"(a[1]), "r"(a[2]), "r"(a[3]), "r"(b0), "r"(b1));
}

// ============================================================
// K1: qcb = emb @ emb_w^T + emb_b   (NT, fp32)
// ============================================================
__global__ __launch_bounds__(256, 2)
void gemm_bias_nt(const float* __restrict__ A, const float* __restrict__ W,
                  const float* __restrict__ bias, int K)
{
    __shared__ float As[16][128];
    __shared__ float Ws[16][128];
    const int tid = threadIdx.x;
    const int tx  = tid & 15;
    const int ty  = tid >> 4;
    const int row0 = blockIdx.y * 128;
    const int col0 = blockIdx.x * 128;

    float acc[8][8];
    #pragma unroll
    for (int i = 0; i < 8; i++)
        #pragma unroll
        for (int j = 0; j < 8; j++) acc[i][j] = 0.0f;

    for (int k0 = 0; k0 < K; k0 += 16) {
        #pragma unroll
        for (int v = tid; v < 512; v += 256) {
            int r  = v >> 2;
            int kc = (v & 3) << 2;
            float4 a = *(const float4*)(A + (size_t)(row0 + r) * K + k0 + kc);
            As[kc + 0][r] = a.x; As[kc + 1][r] = a.y;
            As[kc + 2][r] = a.z; As[kc + 3][r] = a.w;
            float4 w = *(const float4*)(W + (size_t)(col0 + r) * K + k0 + kc);
            Ws[kc + 0][r] = w.x; Ws[kc + 1][r] = w.y;
            Ws[kc + 2][r] = w.z; Ws[kc + 3][r] = w.w;
        }
        __syncthreads();
        #pragma unroll
        for (int kk = 0; kk < 16; kk++) {
            float a[8], b[8];
            *(float4*)(a)     = *(const float4*)&As[kk][ty * 8];
            *(float4*)(a + 4) = *(const float4*)&As[kk][ty * 8 + 4];
            *(float4*)(b)     = *(const float4*)&Ws[kk][tx * 8];
            *(float4*)(b + 4) = *(const float4*)&Ws[kk][tx * 8 + 4];
            #pragma unroll
            for (int i = 0; i < 8; i++)
                #pragma unroll
                for (int j = 0; j < 8; j++)
                    acc[i][j] = fmaf(a[i], b[j], acc[i][j]);
        }
        __syncthreads();
    }

    float bs[8];
    #pragma unroll
    for (int j = 0; j < 8; j++) bs[j] = bias[col0 + tx * 8 + j];

    #pragma unroll
    for (int i = 0; i < 8; i++) {
        size_t row = (size_t)(row0 + ty * 8 + i);
        float* cp = g_qcb + row * DIM + col0 + tx * 8;
        *(float4*)(cp)     = make_float4(acc[i][0]+bs[0], acc[i][1]+bs[1], acc[i][2]+bs[2], acc[i][3]+bs[3]);
        *(float4*)(cp + 4) = make_float4(acc[i][4]+bs[4], acc[i][5]+bs[5], acc[i][6]+bs[6], acc[i][7]+bs[7]);
    }
}

// ============================================================
// K2: per-row 1/||c|| and beta = (z_proj_b . c)/||c||
// ============================================================
__global__ void rownorm_beta(const float* __restrict__ zpb)
{
    int row  = blockIdx.x * 8 + (threadIdx.x >> 5);
    int lane = threadIdx.x & 31;
    const float* x = g_qcb + (size_t)row * DIM;
    float s2 = 0.0f, sb = 0.0f;
    #pragma unroll
    for (int it = 0; it < 4; it++) {
        float4 v = *(const float4*)(x + lane * 4 + it * 128);
        float4 b = *(const float4*)(zpb + lane * 4 + it * 128);
        s2 += v.x*v.x + v.y*v.y + v.z*v.z + v.w*v.w;
        sb += v.x*b.x + v.y*b.y + v.z*b.z + v.w*b.w;
    }
    #pragma unroll
    for (int off = 16; off > 0; off >>= 1) {
        s2 += __shfl_xor_sync(0xFFFFFFFFu, s2, off);
        sb += __shfl_xor_sync(0xFFFFFFFFu, sb, off);
    }
    float rs = 1.0f / fmaxf(sqrtf(s2), 1e-12f);
    if (lane == 0) { g_rs[row] = rs; g_beta[row] = sb * rs; }
}

// ============================================================
// K3: U = (g_qcb @ W) * rs[row]   (NN, fp32) -> g_u fp32 + g_ub f16
// ============================================================
__global__ __launch_bounds__(256, 2)
void gemm_nn_scaled(const float* __restrict__ W)
{
    __shared__ float As[16][128];
    __shared__ float Ws[16][128];
    const int tid = threadIdx.x;
    const int tx  = tid & 15;
    const int ty  = tid >> 4;
    const int row0 = blockIdx.y * 128;
    const int col0 = blockIdx.x * 128;
    const float* __restrict__ A = g_qcb;

    float acc[8][8];
    #pragma unroll
    for (int i = 0; i < 8; i++)
        #pragma unroll
        for (int j = 0; j < 8; j++) acc[i][j] = 0.0f;

    for (int k0 = 0; k0 < DIM; k0 += 16) {
        #pragma unroll
        for (int v = tid; v < 512; v += 256) {
            int r  = v >> 2;
            int kc = (v & 3) << 2;
            float4 a = *(const float4*)(A + (size_t)(row0 + r) * DIM + k0 + kc);
            As[kc + 0][r] = a.x; As[kc + 1][r] = a.y;
            As[kc + 2][r] = a.z; As[kc + 3][r] = a.w;
        }
        #pragma unroll
        for (int v = tid; v < 512; v += 256) {
            int kk = v >> 5;
            int nc = (v & 31) * 4;
            float4 w = *(const float4*)(W + (size_t)(k0 + kk) * DIM + col0 + nc);
            *(float4*)&Ws[kk][nc] = w;
        }
        __syncthreads();
        #pragma unroll
        for (int kk = 0; kk < 16; kk++) {
            float a[8], b[8];
            *(float4*)(a)     = *(const float4*)&As[kk][ty * 8];
            *(float4*)(a + 4) = *(const float4*)&As[kk][ty * 8 + 4];
            *(float4*)(b)     = *(const float4*)&Ws[kk][tx * 8];
            *(float4*)(b + 4) = *(const float4*)&Ws[kk][tx * 8 + 4];
            #pragma unroll
            for (int i = 0; i < 8; i++)
                #pragma unroll
                for (int j = 0; j < 8; j++)
                    acc[i][j] = fmaf(a[i], b[j], acc[i][j]);
        }
        __syncthreads();
    }

    #pragma unroll
    for (int i = 0; i < 8; i++) {
        size_t row = (size_t)(row0 + ty * 8 + i);
        float s = g_rs[row];
        float o[8];
        #pragma unroll
        for (int j = 0; j < 8; j++) o[j] = acc[i][j] * s;
        float* up = g_u + row * DIM + col0 + tx * 8;
        *(float4*)(up)     = make_float4(o[0], o[1], o[2], o[3]);
        *(float4*)(up + 4) = make_float4(o[4], o[5], o[6], o[7]);
        __half2* hp = (__half2*)(g_ub + row * DIM + col0 + tx * 8);
        hp[0] = __floats2half2_rn(o[0], o[1]);
        hp[1] = __floats2half2_rn(o[2], o[3]);
        hp[2] = __floats2half2_rn(o[4], o[5]);
        hp[3] = __floats2half2_rn(o[6], o[7]);
    }
}

// ============================================================
// K4: z -> f16
// ============================================================
__global__ void convert_z(const float* __restrict__ z)
{
    long long n4 = QN / 4;
    long long stride = (long long)gridDim.x * blockDim.x;
    for (long long i = (long long)blockIdx.x * blockDim.x + threadIdx.x; i < n4; i += stride) {
        float4 v = ((const float4*)z)[i];
        __half2 p0 = __floats2half2_rn(v.x, v.y);
        __half2 p1 = __floats2half2_rn(v.z, v.w);
        uint2 o;
        o.x = *(uint32_t*)&p0;
        o.y = *(uint32_t*)&p1;
        ((uint2*)g_zb)[i] = o;
    }
}

// ============================================================
// K5: coarse f16 HMMA pass, k128 B stages, 3-slot ring.
// 256 CTAs x 128 rows. 8 warps, warp tile m16 x n128.
// ============================================================
__global__ __launch_bounds__(256)
void coarse_kernel()
{
    extern __shared__ char sm[];
    const uint32_t smA = smem_u32(sm);
    int* scnt = (int*)(sm + SCNT_OFF);

    const int tid  = threadIdx.x;
    const int lane = tid & 31;
    const int wid  = tid >> 5;
    const int row0 = blockIdx.x * CTA_M;
    const int warp_m = wid << 4;
    const int l8   = lane & 7;
    const int quad = lane >> 3;
    const int lr0  = warp_m + (lane >> 2);

    if (tid < CTA_M) scnt[tid] = 0;

    // ---- A band: 128 rows x 512 f16 (1KB/row), swizzled ----
    #pragma unroll
    for (int i = 0; i < 32; i++) {
        int idx = tid + (i << 8);
        int r = idx >> 6, c = idx & 63;
        const void* src = g_zb + ((size_t)(row0 + r) << 9) + (c << 3);
        uint32_t byte = ((uint32_t)r << 10) + ((uint32_t)c << 4);
        cp16(smA + (byte ^ ((r & 7) << 4)), src);
    }
    // ---- B stage loader: 128 codes x 128 f16 (256B/row), swizzled ----
    auto load_stage = [&](int gs, int slot) {
        const int n0 = (gs >> 2) << 7, k0 = (gs & 3) << 7;   // k0 in f16 elems
        const uint32_t base = smA + SMA_BYTES + (uint32_t)slot * SMB_STAGE;
        #pragma unroll
        for (int i = 0; i < 8; i++) {
            int idx = tid + (i << 8);
            int r = idx >> 4, c = idx & 15;
            const void* src = g_ub + ((size_t)(n0 + r) << 9) + k0 + (c << 3);
            uint32_t byte = ((uint32_t)r << 8) + ((uint32_t)c << 4);
            cp16(base + (byte ^ ((r & 7) << 4)), src);
        }
    };

    load_stage(0, 0); CP_COMMIT();   // group 0: A band + stage 0
    load_stage(1, 1); CP_COMMIT();

    uint32_t acc0[16], acc1[16];     // f16x2 accumulators: rows lr0 / lr0+8
    #pragma unroll
    for (int i = 0; i < 16; i++) { acc0[i] = 0u; acc1[i] = 0u; }

    float best0 = -3.4e38f, best1 = -3.4e38f;
    int slot_c = 0, slot_l = 2;

    for (int gs = 0; gs < NSTAGES_K; gs++) {
        CP_WAIT(1);
        __syncthreads();

        if (gs + 2 < NSTAGES_K) load_stage(gs + 2, slot_l);
        CP_COMMIT();
        slot_l = (slot_l == 2) ? 0 : slot_l + 1;

        const uint32_t sB = smA + SMA_BYTES + (uint32_t)slot_c * SMB_STAGE;
        slot_c = (slot_c == 2) ? 0 : slot_c + 1;
        const int s2 = gs & 3;                 // k128 slice within the n-tile

        #pragma unroll
        for (int s16 = 0; s16 < 8; s16++) {
            uint32_t a[4];
            {
                int m_r = warp_m + l8 + ((quad & 1) << 3);
                int bc  = s2 * 256 + s16 * 32 + ((quad >> 1) << 4);
                ldmatrix_x4(a, smA + ((((uint32_t)m_r << 10) + bc) ^ ((m_r & 7) << 4)));
            }
            #pragma unroll
            for (int ng = 0; ng < 8; ng++) {
                uint32_t b[4];
                int n_r = (ng << 4) + l8 + ((quad & 1) << 3);
                int bc  = s16 * 32 + ((quad >> 1) << 4);
                ldmatrix_x4(b, sB + ((((uint32_t)n_r << 8) + bc) ^ ((n_r & 7) << 4)));
                mma_f16(acc0[2 * ng],     acc1[2 * ng],     a, b[0], b[2]);
                mma_f16(acc0[2 * ng + 1], acc1[2 * ng + 1], a, b[1], b[3]);
            }
        }

        if ((gs & 3) == 3) {
            // ---- tile epilogue: + beta, running argmax, margin emit ----
            const int n0 = (gs >> 2) << 7;
            float t0 = -3.4e38f, t1 = -3.4e38f;
            float s0v[16], s1v[16], s2v[16], s3v[16];
            #pragma unroll
            for (int ni = 0; ni < 16; ni++) {
                int nb = n0 + (ni << 3) + ((lane & 3) << 1);
                float2 be = *(const float2*)(g_beta + nb);
                float2 f0 = __half22float2(*(__half2*)&acc0[ni]);
                float2 f1 = __half22float2(*(__half2*)&acc1[ni]);
                s0v[ni] = f0.x + be.x; s1v[ni] = f0.y + be.y;
                s2v[ni] = f1.x + be.x; s3v[ni] = f1.y + be.y;
                t0 = fmaxf(t0, fmaxf(s0v[ni], s1v[ni]));
                t1 = fmaxf(t1, fmaxf(s2v[ni], s3v[ni]));
                acc0[ni] = 0u; acc1[ni] = 0u;
            }
            t0 = fmaxf(t0, __shfl_xor_sync(0xFFFFFFFFu, t0, 1));
            t0 = fmaxf(t0, __shfl_xor_sync(0xFFFFFFFFu, t0, 2));
            t1 = fmaxf(t1, __shfl_xor_sync(0xFFFFFFFFu, t1, 1));
            t1 = fmaxf(t1, __shfl_xor_sync(0xFFFFFFFFu, t1, 2));
            best0 = fmaxf(best0, t0);
            best1 = fmaxf(best1, t1);
            const float th0 = best0 - MARGIN, th1 = best1 - MARGIN;
            const int gr0 = row0 + lr0;

            #pragma unroll
            for (int ni = 0; ni < 16; ni++) {
                int nb = n0 + (ni << 3) + ((lane & 3) << 1);
                if (s0v[ni] > th0) {
                    int sl = atomicAdd(&scnt[lr0], 1);
                    if (sl < CAP) g_cand[((size_t)gr0 << 6) + sl] = (unsigned)nb;
                }
                if (s1v[ni] > th0) {
                    int sl = atomicAdd(&scnt[lr0], 1);
                    if (sl < CAP) g_cand[((size_t)gr0 << 6) + sl] = (unsigned)(nb + 1);
                }
                if (s2v[ni] > th1) {
                    int sl = atomicAdd(&scnt[lr0 + 8], 1);
                    if (sl < CAP) g_cand[((size_t)(gr0 + 8) << 6) + sl] = (unsigned)nb;
                }
                if (s3v[ni] > th1) {
                    int sl = atomicAdd(&scnt[lr0 + 8], 1);
                    if (sl < CAP) g_cand[((size_t)(gr0 + 8) << 6) + sl] = (unsigned)(nb + 1);
                }
            }
        }
    }

    __syncthreads();
    if (tid < CTA_M) g_ccnt[row0 + tid] = scnt[tid];
}

// ============================================================
// K6: exact fp32 rescore: s = z . u_n + beta_n.  One warp per z-row.
// ============================================================
__global__ __launch_bounds__(256)
void rescore(const float* __restrict__ z)
{
    const int row  = blockIdx.x * 8 + (threadIdx.x >> 5);
    const int lane = threadIdx.x & 31;
    const float* zp = z + (size_t)row * DIM;
    float4 zr[4];
    #pragma unroll
    for (int it = 0; it < 4; it++)
        zr[it] = *(const float4*)(zp + lane * 16 + it * 4);

    int cnt = g_ccnt[row];
    float bv = -3.4e38f;
    int   bi = 0x7FFFFFFF;

    if (cnt <= CAP) {
        for (int c = 0; c < cnt; c++) {
            int idx = (int)g_cand[((size_t)row << 6) + c];
            const float* ur = g_u + (size_t)idx * DIM;
            float s = 0.0f;
            #pragma unroll
            for (int it = 0; it < 4; it++) {
                float4 uv = *(const float4*)(ur + lane * 16 + it * 4);
                s = fmaf(zr[it].x, uv.x, s);
                s = fmaf(zr[it].y, uv.y, s);
                s = fmaf(zr[it].z, uv.z, s);
                s = fmaf(zr[it].w, uv.w, s);
            }
            #pragma unroll
            for (int o = 16; o > 0; o >>= 1) s += __shfl_xor_sync(0xFFFFFFFFu, s, o);
            s += g_beta[idx];
            if (s > bv || (s == bv && idx < bi)) { bv = s; bi = idx; }
        }
    } else {
        for (int n = 0; n < N_CB; n++) {
            const float* ur = g_u + (size_t)n * DIM;
            float s = 0.0f;
            #pragma unroll
            for (int it = 0; it < 4; it++) {
                float4 uv = *(const float4*)(ur + lane * 16 + it * 4);
                s = fmaf(zr[it].x, uv.x, s);
                s = fmaf(zr[it].y, uv.y, s);
                s = fmaf(zr[it].z, uv.z, s);
                s = fmaf(zr[it].w, uv.w, s);
            }
            #pragma unroll
            for (int o = 16; o > 0; o >>= 1) s += __shfl_xor_sync(0xFFFFFFFFu, s, o);
            s += g_beta[n];
            if (s > bv) { bv = s; bi = n; }
        }
    }
    if (lane == 0) g_idx[row] = bi;
}

// ============================================================
// K7: quantized = z + (q - z), per-row (q-z)^2 partial, idx tail
// ============================================================
__global__ void gather_loss(const float* __restrict__ z, float* __restrict__ out,
                            long long out_size)
{
    int row = blockIdx.x;
    int t   = threadIdx.x;   // 128 threads
    int id  = g_idx[row];
    const float* q  = g_qcb + (size_t)id * DIM;
    const float* zr = z + (size_t)row * DIM;
    float* oq = out + (size_t)row * DIM;

    float s = 0.0f;
    #pragma unroll
    for (int c = t * 4; c < DIM; c += 512) {
        float4 qv = *(const float4*)(q + c);
        float4 zv = *(const float4*)(zr + c);
        float4 o;
        float d;
        d = qv.x - zv.x; o.x = zv.x + d; s = fmaf(d, d, s);
        d = qv.y - zv.y; o.y = zv.y + d; s = fmaf(d, d, s);
        d = qv.z - zv.z; o.z = zv.z + d; s = fmaf(d, d, s);
        d = qv.w - zv.w; o.w = zv.w + d; s = fmaf(d, d, s);
        *(float4*)(oq + c) = o;
    }

    __shared__ float red[128];
    red[t] = s;
    __syncthreads();
    #pragma unroll
    for (int off = 64; off > 0; off >>= 1) {
        if (t < off) red[t] += red[t + off];
        __syncthreads();
    }
    if (t == 0) {
        g_partial[row] = red[0];
        long long pos = (long long)QN + 1 + row;
        if (pos < out_size) out[pos] = (float)id;
    }
}

__global__ void finalize_loss(float* __restrict__ out, long long out_size)
{
    __shared__ float red[256];
    int t = threadIdx.x;
    float s = 0.0f;
    for (int i = t; i < M_Z; i += 256) s += g_partial[i];
    red[t] = s;
    __syncthreads();
    #pragma unroll
    for (int off = 128; off > 0; off >>= 1) {
        if (t < off) red[t] += red[t + off];
        __syncthreads();
    }
    if (t == 0 && (long long)QN < out_size)
        out[QN] = red[0] * (1.25f / 16777216.0f);
}

__global__ void zero_range(float* __restrict__ out, long long begin, long long end)
{
    long long stride = (long long)gridDim.x * blockDim.x;
    for (long long i = begin + (long long)blockIdx.x * blockDim.x + threadIdx.x;
         i < end; i += stride)
        out[i] = 0.0f;
}

// ============================================================
extern "C" void kernel_launch(void* const* d_in, const int* in_sizes, int n_in,
                              void* d_out, int out_size)
{
    const float* z     = (const float*)d_in[0];   // [8,4096,512]
    const float* emb   = (const float*)d_in[1];   // [8192,512]
    const float* emb_w = (const float*)d_in[2];   // [512,512]
    const float* emb_b = (const float*)d_in[3];   // [512]
    const float* zw    = (const float*)d_in[4];   // [512,512]
    const float* zb    = (const float*)d_in[5];   // [512]
    // d_in[6] = l2_scale: positive per-row scaling, argmin-invariant -> unused
    float* out = (float*)d_out;
    long long osz = (long long)out_size;

    cudaFuncSetAttribute(coarse_kernel,
                         cudaFuncAttributeMaxDynamicSharedMemorySize, COARSE_SMEM);

    // K1: quant_codebook = emb @ emb_w^T + emb_b
    gemm_bias_nt<<<dim3(4, 64), 256>>>(emb, emb_w, emb_b, DIM);
    // K2: row norms + beta
    rownorm_beta<<<N_CB / 8, 256>>>(zb);
    // K3: U = diag(1/||c||)(qcb @ zw)
    gemm_nn_scaled<<<dim3(4, 64), 256>>>(zw);
    // K4: z -> f16
    convert_z<<<2048, 256>>>(z);
    // K5: f16 HMMA coarse pass -> candidates
    coarse_kernel<<<M_Z / CTA_M, 256, COARSE_SMEM>>>();
    // K6: exact fp32 rescore -> g_idx
    rescore<<<M_Z / 8, 256>>>(z);
    // K7: outputs
    gather_loss<<<M_Z, 128>>>(z, out, osz);
    finalize_loss<<<1, 256>>>(out, osz);
    long long need = (long long)QN + 1 + M_Z;
    if (osz > need) zero_range<<<256, 256>>>(out, need, osz);
}